// round 15
// baseline (speedup 1.0000x reference)
#include <cuda_runtime.h>
#include <cstdint>

// ===========================================================================
// TT-linear via rank-64 bottleneck:  W = A(4096x64) @ B(64x4096)
// Dual-pipe co-execution: tensor (mma.sync tf32) blocks + FMA (fma.f32x2)
// blocks in the SAME launch, split by token rows; uniform split-K=4.
//   t = x @ B^T        y = t @ A^T + b
// ===========================================================================
__device__ __align__(256) float g_A[4096 * 64];     // A (out, r)  tf32-rounded
__device__ __align__(256) float g_G45[64 * 256];    // fold(core4,core5)
__device__ __align__(256) float g_B[64 * 4096];     // B (r, in)   tf32-rounded
__device__ __align__(256) float g_T[4][8192 * 64];  // split-K=4 partials of t

// row splits (64-aligned)
static constexpr int G1_MMA_TILES = 84;   // gemm1 mma: rows [0, 5376)
static constexpr int G1_SIMT_TILES = 44;  // gemm1 simt: rows [5376, 8192)
static constexpr int M1_SPLIT = 5376;
static constexpr int G2_MMA_TILES = 80;   // gemm2 mma: rows [0, 5120)
static constexpr int G2_SIMT_TILES = 48;  // gemm2 simt: rows [5120, 8192)
static constexpr int M2_SPLIT = 5120;

// ---------------- helpers ---------------------------------------------------
__device__ __forceinline__ uint32_t smem_u32(const void* p) {
    uint32_t a;
    asm("{ .reg .u64 t; cvta.to.shared.u64 t, %1; cvt.u32.u64 %0, t; }" : "=r"(a) : "l"(p));
    return a;
}
__device__ __forceinline__ float rna(float v) {
    uint32_t r; asm("cvt.rna.tf32.f32 %0, %1;" : "=r"(r) : "f"(v));
    return __uint_as_float(r);
}
__device__ __forceinline__ void cp16(uint32_t dst, const void* src) {
    asm volatile("cp.async.cg.shared.global [%0], [%1], 16;" :: "r"(dst), "l"(src));
}
#define CP_COMMIT() asm volatile("cp.async.commit_group;" ::: "memory")
#define CP_WAIT1()  asm volatile("cp.async.wait_group 1;" ::: "memory")
#define CP_WAIT0()  asm volatile("cp.async.wait_group 0;" ::: "memory")

__device__ __forceinline__ void mma8(float* c, const uint32_t* a, const uint32_t* b) {
    asm volatile(
        "mma.sync.aligned.m16n8k8.row.col.f32.tf32.tf32.f32 "
        "{%0,%1,%2,%3}, {%4,%5,%6,%7}, {%8,%9}, {%0,%1,%2,%3};"
        : "+f"(c[0]), "+f"(c[1]), "+f"(c[2]), "+f"(c[3])
        : "r"(a[0]), "r"(a[1]), "r"(a[2]), "r"(a[3]), "r"(b[0]), "r"(b[1]));
}

__device__ __forceinline__ float2 ffma2(float2 a, float2 b, float2 c) {
    unsigned long long ra = *reinterpret_cast<unsigned long long*>(&a);
    unsigned long long rb = *reinterpret_cast<unsigned long long*>(&b);
    unsigned long long rc = *reinterpret_cast<unsigned long long*>(&c);
    unsigned long long rd;
    asm("fma.rn.f32x2 %0, %1, %2, %3;" : "=l"(rd) : "l"(ra), "l"(rb), "l"(rc));
    return *reinterpret_cast<float2*>(&rd);
}

// ---------------------------------------------------------------------------
// Folds (proven). Cores: G0(1,16,64) G1..G4(64,16,64) G5(64,16,1).
// ---------------------------------------------------------------------------
__global__ void foldG45_kernel(const float* __restrict__ G4, const float* __restrict__ G5) {
    int i = blockIdx.x * 256 + threadIdx.x;
    int r4 = i >> 8, s4 = (i >> 4) & 15, s5 = i & 15;
    float s = 0.f;
#pragma unroll
    for (int r5 = 0; r5 < 64; ++r5) s += G4[r4 * 1024 + s4 * 64 + r5] * G5[r5 * 16 + s5];
    g_G45[i] = s;
}

__global__ __launch_bounds__(256) void foldB12_kernel(const float* __restrict__ G3,
                                                      const float* __restrict__ G0,
                                                      const float* __restrict__ G1,
                                                      const float* __restrict__ G2) {
    const int tid = threadIdx.x;
    if (blockIdx.x < 1024) {
        const int b = blockIdx.x, c = tid;
        float a0 = 0.f, a1 = 0.f, a2 = 0.f, a3 = 0.f;
#pragma unroll
        for (int r4 = 0; r4 < 64; r4 += 4) {
            a0 += G3[b * 64 + r4]     * g_G45[r4 * 256 + c];
            a1 += G3[b * 64 + r4 + 1] * g_G45[(r4 + 1) * 256 + c];
            a2 += G3[b * 64 + r4 + 2] * g_G45[(r4 + 2) * 256 + c];
            a3 += G3[b * 64 + r4 + 3] * g_G45[(r4 + 3) * 256 + c];
        }
        g_B[(size_t)b * 256 + c] = rna((a0 + a1) + (a2 + a3));
    } else {
        __shared__ float w01row[64];
        const int b = blockIdx.x - 1024;
        const int r = b >> 2, s0 = r >> 4, s1 = r & 15;
        if (tid < 64) {
            float s = 0.f;
#pragma unroll
            for (int r1 = 0; r1 < 64; ++r1)
                s += G0[s0 * 64 + r1] * G1[r1 * 1024 + s1 * 64 + tid];
            w01row[tid] = s;
        }
        __syncthreads();
        const int c = (b & 3) * 256 + tid;
        float a0 = 0.f, a1 = 0.f, a2 = 0.f, a3 = 0.f;
#pragma unroll
        for (int r2 = 0; r2 < 64; r2 += 4) {
            a0 += w01row[r2]     * G2[r2 * 1024 + c];
            a1 += w01row[r2 + 1] * G2[(r2 + 1) * 1024 + c];
            a2 += w01row[r2 + 2] * G2[(r2 + 2) * 1024 + c];
            a3 += w01row[r2 + 3] * G2[(r2 + 3) * 1024 + c];
        }
        g_A[(size_t)r * 1024 + c] = rna((a0 + a1) + (a2 + a3));
    }
}

// ---------------------------------------------------------------------------
// GEMM1 dual-pipe: t[n,r] = sum_k x[n,k]*B[r,k].  M=8192 N=64 K=4096.
// 1-D grid, 256 threads, dsmem 55296.
//  bx < 336: mma block [R7 config]: tile=bx>>2, ky=bx&3; 64tok x 64r, K=1024,
//            8 warps 4x2 (warp 16x32), 32 chunks of 32, 3-stage cp.async ring.
//  bx >=336: SIMT block [R1 config]: idx=bx-336; tile=idx>>2, kq=idx&3;
//            64tok x 64r, K=1024, 16x16 threads, tile 4tok x 4r, fma.f32x2.
// ---------------------------------------------------------------------------
__global__ __launch_bounds__(256) void gemm1_kernel(const float* __restrict__ x) {
    extern __shared__ char sm[];
    const int tid = threadIdx.x;

    if (blockIdx.x < G1_MMA_TILES * 4) {
        // ================== mma path (tensor pipe) ==================
        const uint32_t sb = smem_u32(sm);
        const int warp = tid >> 5, lane = tid & 31;
        const int wm = warp >> 1, wn = warp & 1;      // warp origin (wm*16, wn*32)
        const int tok0 = (blockIdx.x >> 2) * 64;
        const int ky = blockIdx.x & 3;
        const int kbase = ky * 1024;
        const int qr = (tid & 7) * 4;
        const int row0 = tid >> 3;                    // 0..31

        float acc[4][4];
#pragma unroll
        for (int b = 0; b < 4; ++b)
#pragma unroll
            for (int c = 0; c < 4; ++c) acc[b][c] = 0.f;

        auto issue = [&](int chunk, int s) {
            int kc = kbase + chunk * 32;
            uint32_t xd = sb + s * 18432;
            uint32_t bd = xd + 9216;
#pragma unroll
            for (int l = 0; l < 2; ++l) {
                int r = row0 + 32 * l;
                cp16(xd + (uint32_t)(r * 144 + qr * 4), &x[(size_t)(tok0 + r) * 4096 + kbase + chunk * 32 + qr]);
                cp16(bd + (uint32_t)(r * 144 + qr * 4), &g_B[(size_t)r * 4096 + kc + qr]);
            }
        };

        issue(0, 0); CP_COMMIT();
        issue(1, 1); CP_COMMIT();

        const int lr = lane >> 2, lc = lane & 3;
        int stage = 0;
        for (int i = 0; i < 32; ++i) {
            CP_WAIT1();
            __syncthreads();
            if (i + 2 < 32) issue(i + 2, (stage + 2) % 3);
            CP_COMMIT();

            const float* xs = reinterpret_cast<const float*>(sm + stage * 18432);
            const float* bs = reinterpret_cast<const float*>(sm + stage * 18432 + 9216);
#pragma unroll
            for (int k8 = 0; k8 < 4; ++k8) {
                const int kk = k8 * 8 + lc;
                uint32_t af[4], bf[4][2];
                {
                    int r = wm * 16 + lr;
                    af[0] = __float_as_uint(xs[r * 36 + kk]);
                    af[1] = __float_as_uint(xs[(r + 8) * 36 + kk]);
                    af[2] = __float_as_uint(xs[r * 36 + kk + 4]);
                    af[3] = __float_as_uint(xs[(r + 8) * 36 + kk + 4]);
                }
#pragma unroll
                for (int nt = 0; nt < 4; ++nt) {
                    int n = wn * 32 + nt * 8 + lr;
                    bf[nt][0] = __float_as_uint(bs[n * 36 + kk]);
                    bf[nt][1] = __float_as_uint(bs[n * 36 + kk + 4]);
                }
#pragma unroll
                for (int nt = 0; nt < 4; ++nt) mma8(acc[nt], af, bf[nt]);
            }
            stage = (stage + 1) % 3;
        }

        float* tp = g_T[ky];
#pragma unroll
        for (int nt = 0; nt < 4; ++nt)
#pragma unroll
            for (int h = 0; h < 2; ++h) {
                int r = tok0 + wm * 16 + lr + 8 * h;
                int c = wn * 32 + nt * 8 + 2 * lc;
                *reinterpret_cast<float2*>(&tp[(size_t)r * 64 + c]) =
                    make_float2(acc[nt][2 * h], acc[nt][2 * h + 1]);
            }
    } else {
        // ================== SIMT path (FMA pipe) ==================
        float* sx = reinterpret_cast<float*>(sm);            // [64][33]
        float* sbf = sx + 64 * 33;                           // [64][33]
        const int idx = blockIdx.x - G1_MMA_TILES * 4;
        const int tok0 = M1_SPLIT + (idx >> 2) * 64;
        const int kq = idx & 3;
        const int kbase = kq * 1024;
        const int tx = tid & 15;       // r = tx + 16j
        const int ty = tid >> 4;       // tokens ty*4 .. ty*4+3

        float2 acc[4][2];
#pragma unroll
        for (int i = 0; i < 4; ++i) { acc[i][0] = make_float2(0.f, 0.f); acc[i][1] = make_float2(0.f, 0.f); }

        for (int k0 = kbase; k0 < kbase + 1024; k0 += 32) {
#pragma unroll
            for (int l = 0; l < 2; ++l) {
                int s = tid + 256 * l, row = s >> 3, kq4 = (s & 7) << 2;
                float4 v = *reinterpret_cast<const float4*>(&x[(size_t)(tok0 + row) * 4096 + k0 + kq4]);
                sx[row * 33 + kq4 + 0] = v.x; sx[row * 33 + kq4 + 1] = v.y;
                sx[row * 33 + kq4 + 2] = v.z; sx[row * 33 + kq4 + 3] = v.w;
                float4 w = *reinterpret_cast<const float4*>(&g_B[(size_t)row * 4096 + k0 + kq4]);
                sbf[row * 33 + kq4 + 0] = w.x; sbf[row * 33 + kq4 + 1] = w.y;
                sbf[row * 33 + kq4 + 2] = w.z; sbf[row * 33 + kq4 + 3] = w.w;
            }
            __syncthreads();
#pragma unroll
            for (int kk = 0; kk < 32; ++kk) {
                float a[4];
#pragma unroll
                for (int i = 0; i < 4; ++i) a[i] = sx[(ty * 4 + i) * 33 + kk];
                float2 bp0 = make_float2(sbf[tx * 33 + kk],        sbf[(tx + 16) * 33 + kk]);
                float2 bp1 = make_float2(sbf[(tx + 32) * 33 + kk], sbf[(tx + 48) * 33 + kk]);
#pragma unroll
                for (int i = 0; i < 4; ++i) {
                    float2 av = make_float2(a[i], a[i]);
                    acc[i][0] = ffma2(av, bp0, acc[i][0]);
                    acc[i][1] = ffma2(av, bp1, acc[i][1]);
                }
            }
            __syncthreads();
        }
#pragma unroll
        for (int i = 0; i < 4; ++i) {
            int n = tok0 + ty * 4 + i;
            float* tr = &g_T[kq][(size_t)n * 64];
            tr[tx]      = acc[i][0].x;
            tr[tx + 16] = acc[i][0].y;
            tr[tx + 32] = acc[i][1].x;
            tr[tx + 48] = acc[i][1].y;
        }
    }
}

// ---------------------------------------------------------------------------
// GEMM2 dual-pipe: y[n,o] = sum_r t[n,r]*A[o,r] + b[o].  M=8192 N=4096 K=64.
// 1-D grid, 256 threads, dsmem 87040.
//  bx < 640:  mma block [R14 config]: tile=bx>>3 (64 tok), oc=bx&7 (512 outs
//             as 4 chunks of 128, A dbl-buffered).
//  bx >= 640: SIMT block: idx=bx-640; 64tok x 128out, fma.f32x2.
// Both paths sum all 4 t-partials.
// ---------------------------------------------------------------------------
__global__ __launch_bounds__(256) void gemm2_kernel(const float* __restrict__ bias,
                                                    float* __restrict__ y) {
    extern __shared__ char sm[];
    const int tid = threadIdx.x;

    if (blockIdx.x < G2_MMA_TILES * 8) {
        // ================== mma path (tensor pipe) ==================
        float* st = reinterpret_cast<float*>(sm);
        const uint32_t sb = smem_u32(sm);
        const int warp = tid >> 5, lane = tid & 31;
        const int wm = warp >> 2, wn = warp & 3;      // warp origin (wm*32, wn*32)
        const int tok0 = (blockIdx.x >> 3) * 64;
        const int outbase = (blockIdx.x & 7) * 512;
        const int lr = lane >> 2, lc = lane & 3;

        auto issueA = [&](int chunk, int buf) {
            const float* src = &g_A[(size_t)(outbase + chunk * 128) * 64];
            uint32_t base = sb + 17408 + buf * 34816;
#pragma unroll
            for (int l = 0; l < 8; ++l) {
                int s = tid + 256 * l;
                int row = s >> 4, q = (s & 15) * 4;
                cp16(base + (uint32_t)(row * 272 + q * 4), src + (size_t)row * 64 + q);
            }
        };

        issueA(0, 0); CP_COMMIT();

#pragma unroll
        for (int l = 0; l < 4; ++l) {
            int s = tid + 256 * l, row = s >> 4, q = (s & 15) * 4;
            size_t off = (size_t)(tok0 + row) * 64 + q;
            float4 v0 = *reinterpret_cast<const float4*>(&g_T[0][off]);
            float4 v1 = *reinterpret_cast<const float4*>(&g_T[1][off]);
            float4 v2 = *reinterpret_cast<const float4*>(&g_T[2][off]);
            float4 v3 = *reinterpret_cast<const float4*>(&g_T[3][off]);
            st[row * 68 + q + 0] = rna((v0.x + v1.x) + (v2.x + v3.x));
            st[row * 68 + q + 1] = rna((v0.y + v1.y) + (v2.y + v3.y));
            st[row * 68 + q + 2] = rna((v0.z + v1.z) + (v2.z + v3.z));
            st[row * 68 + q + 3] = rna((v0.w + v1.w) + (v2.w + v3.w));
        }

#pragma unroll
        for (int c = 0; c < 4; ++c) {
            if (c < 3) { issueA(c + 1, (c + 1) & 1); CP_COMMIT(); CP_WAIT1(); }
            else       { CP_WAIT0(); }
            __syncthreads();

            const float* sa = reinterpret_cast<const float*>(sm + 17408 + (c & 1) * 34816);
            const int out0 = outbase + c * 128;

            float acc[2][4][4];
#pragma unroll
            for (int a = 0; a < 2; ++a)
#pragma unroll
                for (int b = 0; b < 4; ++b)
#pragma unroll
                    for (int q = 0; q < 4; ++q) acc[a][b][q] = 0.f;

#pragma unroll
            for (int k8 = 0; k8 < 8; ++k8) {
                const int kk = k8 * 8 + lc;
                uint32_t af[2][4], bf[4][2];
#pragma unroll
                for (int mt = 0; mt < 2; ++mt) {
                    int r = wm * 32 + mt * 16 + lr;
                    af[mt][0] = __float_as_uint(st[r * 68 + kk]);
                    af[mt][1] = __float_as_uint(st[(r + 8) * 68 + kk]);
                    af[mt][2] = __float_as_uint(st[r * 68 + kk + 4]);
                    af[mt][3] = __float_as_uint(st[(r + 8) * 68 + kk + 4]);
                }
#pragma unroll
                for (int nt = 0; nt < 4; ++nt) {
                    int n = wn * 32 + nt * 8 + lr;
                    bf[nt][0] = __float_as_uint(sa[n * 68 + kk]);
                    bf[nt][1] = __float_as_uint(sa[n * 68 + kk + 4]);
                }
#pragma unroll
                for (int mt = 0; mt < 2; ++mt)
#pragma unroll
                    for (int nt = 0; nt < 4; ++nt) mma8(acc[mt][nt], af[mt], bf[nt]);
            }

            float2 bv[4];
#pragma unroll
            for (int nt = 0; nt < 4; ++nt)
                bv[nt] = *reinterpret_cast<const float2*>(&bias[out0 + wn * 32 + nt * 8 + 2 * lc]);

#pragma unroll
            for (int mt = 0; mt < 2; ++mt)
#pragma unroll
                for (int h = 0; h < 2; ++h) {
                    int r = tok0 + wm * 32 + mt * 16 + lr + 8 * h;
                    float* yr = y + (size_t)r * 4096 + out0 + wn * 32;
#pragma unroll
                    for (int nt = 0; nt < 4; ++nt) {
                        *reinterpret_cast<float2*>(&yr[nt * 8 + 2 * lc]) =
                            make_float2(acc[mt][nt][2 * h] + bv[nt].x,
                                        acc[mt][nt][2 * h + 1] + bv[nt].y);
                    }
                }
            __syncthreads();
        }
    } else {
        // ================== SIMT path (FMA pipe) ==================
        float* st = reinterpret_cast<float*>(sm);              // [64][65]
        float* sa = reinterpret_cast<float*>(sm) + 64 * 65;    // [128][65]
        const int idx = blockIdx.x - G2_MMA_TILES * 8;
        const int tok0 = M2_SPLIT + (idx >> 5) * 64;
        const int out0 = (idx & 31) * 128;
        const int tx = tid & 15;
        const int ty = tid >> 4;

        // t tile: sum 4 partials (raw fp32). 64x64 = 1024 f4 slots.
#pragma unroll
        for (int l = 0; l < 4; ++l) {
            int s = tid + 256 * l, row = s >> 4, c = (s & 15) * 4;
            size_t off = (size_t)(tok0 + row) * 64 + c;
            float4 v0 = *reinterpret_cast<const float4*>(&g_T[0][off]);
            float4 v1 = *reinterpret_cast<const float4*>(&g_T[1][off]);
            float4 v2 = *reinterpret_cast<const float4*>(&g_T[2][off]);
            float4 v3 = *reinterpret_cast<const float4*>(&g_T[3][off]);
            st[row * 65 + c + 0] = (v0.x + v1.x) + (v2.x + v3.x);
            st[row * 65 + c + 1] = (v0.y + v1.y) + (v2.y + v3.y);
            st[row * 65 + c + 2] = (v0.z + v1.z) + (v2.z + v3.z);
            st[row * 65 + c + 3] = (v0.w + v1.w) + (v2.w + v3.w);
        }
        // A tile 128x64 = 2048 f4 slots
#pragma unroll
        for (int l = 0; l < 8; ++l) {
            int s = tid + 256 * l, row = s >> 4, c = (s & 15) * 4;
            float4 v = *reinterpret_cast<const float4*>(&g_A[(size_t)(out0 + row) * 64 + c]);
            sa[row * 65 + c + 0] = v.x; sa[row * 65 + c + 1] = v.y;
            sa[row * 65 + c + 2] = v.z; sa[row * 65 + c + 3] = v.w;
        }
        __syncthreads();

        float2 acc[4][4];
#pragma unroll
        for (int i = 0; i < 4; ++i)
#pragma unroll
            for (int p = 0; p < 4; ++p) acc[i][p] = make_float2(0.f, 0.f);

#pragma unroll
        for (int r = 0; r < 64; ++r) {
            float a[4];
#pragma unroll
            for (int i = 0; i < 4; ++i) a[i] = st[(ty * 4 + i) * 65 + r];
            float2 bp[4];
#pragma unroll
            for (int p = 0; p < 4; ++p)
                bp[p] = make_float2(sa[(tx + 16 * (2 * p)) * 65 + r],
                                    sa[(tx + 16 * (2 * p + 1)) * 65 + r]);
#pragma unroll
            for (int i = 0; i < 4; ++i) {
                float2 av = make_float2(a[i], a[i]);
#pragma unroll
                for (int p = 0; p < 4; ++p) acc[i][p] = ffma2(av, bp[p], acc[i][p]);
            }
        }

        float bv[8];
#pragma unroll
        for (int jj = 0; jj < 8; ++jj) bv[jj] = bias[out0 + tx + 16 * jj];

#pragma unroll
        for (int i = 0; i < 4; ++i) {
            int n = tok0 + ty * 4 + i;
            float* yr = y + (size_t)n * 4096 + out0;
#pragma unroll
            for (int p = 0; p < 4; ++p) {
                yr[tx + 16 * (2 * p)]     = acc[i][p].x + bv[2 * p];
                yr[tx + 16 * (2 * p + 1)] = acc[i][p].y + bv[2 * p + 1];
            }
        }
    }
}

// ---------------------------------------------------------------------------
// Launch
// ---------------------------------------------------------------------------
extern "C" void kernel_launch(void* const* d_in, const int* in_sizes, int n_in,
                              void* d_out, int out_size) {
    const float* core[6] = {nullptr, nullptr, nullptr, nullptr, nullptr, nullptr};
    const float* x = nullptr;
    const float* bias = nullptr;
    int c64 = 1;
    for (int i = 0; i < n_in; ++i) {
        int sz = in_sizes[i];
        const float* p = reinterpret_cast<const float*>(d_in[i]);
        if (sz == 8192 * 4096) x = p;
        else if (sz == 4096) bias = p;
        else if (sz == 65536) { if (c64 <= 4) core[c64++] = p; }
        else if (sz == 1024) { if (!core[0]) core[0] = p; else core[5] = p; }
    }
    float* y = reinterpret_cast<float*>(d_out);

    const int g1_smem = 3 * 18432;              // 55296
    const int g2_smem = 17408 + 2 * 34816;      // 87040
    cudaFuncSetAttribute(gemm1_kernel, cudaFuncAttributeMaxDynamicSharedMemorySize, g1_smem);
    cudaFuncSetAttribute(gemm2_kernel, cudaFuncAttributeMaxDynamicSharedMemorySize, g2_smem);
    cudaFuncSetAttribute(gemm1_kernel, cudaFuncAttributePreferredSharedMemoryCarveout, 100);
    cudaFuncSetAttribute(gemm2_kernel, cudaFuncAttributePreferredSharedMemoryCarveout, 100);

    foldG45_kernel<<<64, 256>>>(core[4], core[5]);
    foldB12_kernel<<<2048, 256>>>(core[3], core[0], core[1], core[2]);
    gemm1_kernel<<<G1_MMA_TILES * 4 + G1_SIMT_TILES * 4, 256, g1_smem>>>(x);
    gemm2_kernel<<<G2_MMA_TILES * 8 + G2_SIMT_TILES * 32, 256, g2_smem>>>(bias, y);
}

// round 16
// speedup vs baseline: 1.3285x; 1.3285x over previous
#include <cuda_runtime.h>
#include <cstdint>

// ===========================================================================
// TT-linear via rank-64 bottleneck:  W = A(4096x64) @ B(64x4096)
//   t = x @ B^T      (mma.sync tf32, split-K=2, 4-stage ring)  [R6, 48.2us]
//                    + fold12(A) on the 20 idle SMs (bids 128..147)
//   y = t @ A^T + b  (mma.sync tf32, 64tok x 4x128out, A dbl-buf) [R14, 50.7us]
// Tensor instruction floor reached (~26 cyc/mma/SMSP); this round harvests
// fold/launch slack only.
// ===========================================================================
__device__ __align__(256) float g_A[4096 * 64];     // A (out, r)  tf32-rounded
__device__ __align__(256) float g_G45[64 * 256];    // fold(core4,core5)
__device__ __align__(256) float g_B[64 * 4096];     // B (r, in)   tf32-rounded
__device__ __align__(256) float g_T[2][8192 * 64];  // split-K=2 partials of t

// ---------------- helpers ---------------------------------------------------
__device__ __forceinline__ uint32_t smem_u32(const void* p) {
    uint32_t a;
    asm("{ .reg .u64 t; cvta.to.shared.u64 t, %1; cvt.u32.u64 %0, t; }" : "=r"(a) : "l"(p));
    return a;
}
__device__ __forceinline__ float rna(float v) {
    uint32_t r; asm("cvt.rna.tf32.f32 %0, %1;" : "=r"(r) : "f"(v));
    return __uint_as_float(r);
}
__device__ __forceinline__ void cp16(uint32_t dst, const void* src) {
    asm volatile("cp.async.cg.shared.global [%0], [%1], 16;" :: "r"(dst), "l"(src));
}
#define CP_COMMIT() asm volatile("cp.async.commit_group;" ::: "memory")
#define CP_WAIT2()  asm volatile("cp.async.wait_group 2;" ::: "memory")
#define CP_WAIT1()  asm volatile("cp.async.wait_group 1;" ::: "memory")
#define CP_WAIT0()  asm volatile("cp.async.wait_group 0;" ::: "memory")

__device__ __forceinline__ void mma8(float* c, const uint32_t* a, const uint32_t* b) {
    asm volatile(
        "mma.sync.aligned.m16n8k8.row.col.f32.tf32.tf32.f32 "
        "{%0,%1,%2,%3}, {%4,%5,%6,%7}, {%8,%9}, {%0,%1,%2,%3};"
        : "+f"(c[0]), "+f"(c[1]), "+f"(c[2]), "+f"(c[3])
        : "r"(a[0]), "r"(a[1]), "r"(a[2]), "r"(a[3]), "r"(b[0]), "r"(b[1]));
}

// ---------------------------------------------------------------------------
// Folds. Cores: G0(1,16,64) G1..G4(64,16,64) G5(64,16,1).
// ---------------------------------------------------------------------------
__global__ void foldG45_kernel(const float* __restrict__ G4, const float* __restrict__ G5) {
    int i = blockIdx.x * 256 + threadIdx.x;       // 16384: G45[r4][(s4,s5)]
    int r4 = i >> 8, s4 = (i >> 4) & 15, s5 = i & 15;
    float s = 0.f;
#pragma unroll
    for (int r5 = 0; r5 < 64; ++r5) s += G4[r4 * 1024 + s4 * 64 + r5] * G5[r5 * 16 + s5];
    g_G45[i] = s;
}

// B[(r3,s3)][(s4,s5)]: flat (1024,256) == (64,4096) row-major.
__global__ __launch_bounds__(256) void foldB_kernel(const float* __restrict__ G3) {
    const int b = blockIdx.x, c = threadIdx.x;
    float a0 = 0.f, a1 = 0.f, a2 = 0.f, a3 = 0.f;
#pragma unroll
    for (int r4 = 0; r4 < 64; r4 += 4) {
        a0 += G3[b * 64 + r4]     * g_G45[r4 * 256 + c];
        a1 += G3[b * 64 + r4 + 1] * g_G45[(r4 + 1) * 256 + c];
        a2 += G3[b * 64 + r4 + 2] * g_G45[(r4 + 2) * 256 + c];
        a3 += G3[b * 64 + r4 + 3] * g_G45[(r4 + 3) * 256 + c];
    }
    g_B[(size_t)b * 256 + c] = rna((a0 + a1) + (a2 + a3));
}

// ---------------------------------------------------------------------------
// GEMM1 [R6 body] + fold12 on idle SMs: t[n,r] = sum_k x[n,k]*B[r,k].
// M=8192 N=64 K=4096, split-K=2. 1-D grid 148, 256 threads, dsmem 110592.
//  bx < 128: gemm1 CTA: tile = bx>>1 (128 tok), ky = bx&1 (K half).
//            8 warps 4x2, warp 32x32, K chunks of 32, 4-stage cp.async ring.
//  bx >= 128: fold12 block (A path): rows of flat A (256,1024) -> g_A.
//            20 blocks; co-resident with gemm1 (110KB*2 = 216KB < 228KB).
// ---------------------------------------------------------------------------
__global__ __launch_bounds__(256) void gemm1_kernel(const float* __restrict__ x,
                                                    const float* __restrict__ G0,
                                                    const float* __restrict__ G1,
                                                    const float* __restrict__ G2) {
    extern __shared__ char sm[];
    const int tid = threadIdx.x;

    if (blockIdx.x >= 128) {
        // ============ fold12 (A): runs on the 20 SMs gemm1 leaves idle ======
        __shared__ float w01row[64];
        const int b = blockIdx.x - 128;           // 0..19
        const int start = (b < 16) ? b * 13 : 208 + (b - 16) * 12;
        const int count = (b < 16) ? 13 : 12;
        for (int it = 0; it < count; ++it) {
            const int r = start + it;             // flat-A row 0..255
            const int s0 = r >> 4, s1 = r & 15;
            if (tid < 64) {
                float s = 0.f;
#pragma unroll
                for (int r1 = 0; r1 < 64; ++r1)
                    s += G0[s0 * 64 + r1] * G1[r1 * 1024 + s1 * 64 + tid];
                w01row[tid] = s;
            }
            __syncthreads();
#pragma unroll
            for (int q = 0; q < 4; ++q) {
                const int c = q * 256 + tid;
                float a0 = 0.f, a1 = 0.f;
#pragma unroll
                for (int r2 = 0; r2 < 64; r2 += 2) {
                    a0 += w01row[r2]     * G2[r2 * 1024 + c];
                    a1 += w01row[r2 + 1] * G2[(r2 + 1) * 1024 + c];
                }
                g_A[(size_t)r * 1024 + c] = rna(a0 + a1);
            }
            __syncthreads();
        }
        return;
    }

    // ================= gemm1 mma body (R6, unchanged) =======================
    const uint32_t sb = smem_u32(sm);
    const int warp = tid >> 5, lane = tid & 31;
    const int wm = warp >> 1, wn = warp & 1;      // warp origin (wm*32, wn*32)
    const int tok0 = (blockIdx.x >> 1) * 128;
    const int ky = blockIdx.x & 1;
    const int kbase = ky * 2048;
    const int qr = (tid & 7) * 4;
    const int row0 = tid >> 3;                    // 0..31

    float acc[2][4][4];
#pragma unroll
    for (int a = 0; a < 2; ++a)
#pragma unroll
        for (int b = 0; b < 4; ++b)
#pragma unroll
            for (int c = 0; c < 4; ++c) acc[a][b][c] = 0.f;

    auto issue = [&](int chunk, int s) {
        int kc = kbase + chunk * 32;
        uint32_t xd = sb + s * 27648;
        uint32_t bd = xd + 18432;
#pragma unroll
        for (int l = 0; l < 4; ++l) {
            int r = row0 + 32 * l;
            cp16(xd + (uint32_t)(r * 144 + qr * 4), &x[(size_t)(tok0 + r) * 4096 + kc + qr]);
        }
#pragma unroll
        for (int l = 0; l < 2; ++l) {
            int r = row0 + 32 * l;
            cp16(bd + (uint32_t)(r * 144 + qr * 4), &g_B[(size_t)r * 4096 + kc + qr]);
        }
    };

    issue(0, 0); CP_COMMIT();
    issue(1, 1); CP_COMMIT();
    issue(2, 2); CP_COMMIT();

    const int lr = lane >> 2, lc = lane & 3;
    for (int i = 0; i < 64; ++i) {
        CP_WAIT2();
        __syncthreads();
        if (i + 3 < 64) issue(i + 3, (i + 3) & 3);
        CP_COMMIT();    // empty group at tail keeps wait_group 2 uniform

        const float* xs = reinterpret_cast<const float*>(sm + (i & 3) * 27648);
        const float* bs = reinterpret_cast<const float*>(sm + (i & 3) * 27648 + 18432);
#pragma unroll
        for (int k8 = 0; k8 < 4; ++k8) {
            const int kk = k8 * 8 + lc;
            uint32_t af[2][4], bf[4][2];
#pragma unroll
            for (int mt = 0; mt < 2; ++mt) {
                int r = wm * 32 + mt * 16 + lr;
                af[mt][0] = __float_as_uint(xs[r * 36 + kk]);
                af[mt][1] = __float_as_uint(xs[(r + 8) * 36 + kk]);
                af[mt][2] = __float_as_uint(xs[r * 36 + kk + 4]);
                af[mt][3] = __float_as_uint(xs[(r + 8) * 36 + kk + 4]);
            }
#pragma unroll
            for (int nt = 0; nt < 4; ++nt) {
                int n = wn * 32 + nt * 8 + lr;
                bf[nt][0] = __float_as_uint(bs[n * 36 + kk]);
                bf[nt][1] = __float_as_uint(bs[n * 36 + kk + 4]);
            }
#pragma unroll
            for (int mt = 0; mt < 2; ++mt)
#pragma unroll
                for (int nt = 0; nt < 4; ++nt) mma8(acc[mt][nt], af[mt], bf[nt]);
        }
    }

    float* tp = g_T[ky];
#pragma unroll
    for (int mt = 0; mt < 2; ++mt)
#pragma unroll
        for (int nt = 0; nt < 4; ++nt)
#pragma unroll
            for (int h = 0; h < 2; ++h) {
                int r = tok0 + wm * 32 + mt * 16 + lr + 8 * h;
                int c = wn * 32 + nt * 8 + 2 * lc;
                *reinterpret_cast<float2*>(&tp[(size_t)r * 64 + c]) =
                    make_float2(acc[mt][nt][2 * h], acc[mt][nt][2 * h + 1]);
            }
}

// ---------------------------------------------------------------------------
// GEMM2 [R14 exact, 50.7us]: y[n,o] = sum_r t[n,r]*A[o,r] + b[o].
// grid (128,8) = 1024 CTAs, 256 threads, 8 warps 2x4 (warp 32x32/chunk).
// CTA: 64 tok x 512 outs as 4 chunks of 128; t loaded once; A dbl-buffered.
// smem: st[64][68] @0, A bufs @17408/@52224 -> 87040 B, 2 CTAs/SM.
// ---------------------------------------------------------------------------
__global__ __launch_bounds__(256, 2) void gemm2_kernel(const float* __restrict__ bias,
                                                       float* __restrict__ y) {
    extern __shared__ char sm[];
    float* st = reinterpret_cast<float*>(sm);
    const uint32_t sb = smem_u32(sm);
    const int tid = threadIdx.x;
    const int warp = tid >> 5, lane = tid & 31;
    const int wm = warp >> 2, wn = warp & 3;      // warp origin (wm*32, wn*32)
    const int tok0 = blockIdx.x * 64;
    const int outbase = blockIdx.y * 512;
    const int lr = lane >> 2, lc = lane & 3;

    auto issueA = [&](int chunk, int buf) {
        const float* src = &g_A[(size_t)(outbase + chunk * 128) * 64];
        uint32_t base = sb + 17408 + buf * 34816;
#pragma unroll
        for (int l = 0; l < 8; ++l) {
            int s = tid + 256 * l;        // 0..2047
            int row = s >> 4, q = (s & 15) * 4;
            cp16(base + (uint32_t)(row * 272 + q * 4), src + (size_t)row * 64 + q);
        }
    };

    issueA(0, 0); CP_COMMIT();

    // t tile: reduce split-K partials, round to tf32 (overlaps A0 fetch)
#pragma unroll
    for (int l = 0; l < 4; ++l) {
        int s = tid + 256 * l, row = s >> 4, q = (s & 15) * 4;
        size_t off = (size_t)(tok0 + row) * 64 + q;
        float4 v0 = *reinterpret_cast<const float4*>(&g_T[0][off]);
        float4 v1 = *reinterpret_cast<const float4*>(&g_T[1][off]);
        st[row * 68 + q + 0] = rna(v0.x + v1.x);
        st[row * 68 + q + 1] = rna(v0.y + v1.y);
        st[row * 68 + q + 2] = rna(v0.z + v1.z);
        st[row * 68 + q + 3] = rna(v0.w + v1.w);
    }

#pragma unroll
    for (int c = 0; c < 4; ++c) {
        if (c < 3) { issueA(c + 1, (c + 1) & 1); CP_COMMIT(); CP_WAIT1(); }
        else       { CP_WAIT0(); }
        __syncthreads();      // chunk c ready for all warps

        const float* sa = reinterpret_cast<const float*>(sm + 17408 + (c & 1) * 34816);
        const int out0 = outbase + c * 128;

        float acc[2][4][4];
#pragma unroll
        for (int a = 0; a < 2; ++a)
#pragma unroll
            for (int b = 0; b < 4; ++b)
#pragma unroll
                for (int q = 0; q < 4; ++q) acc[a][b][q] = 0.f;

#pragma unroll
        for (int k8 = 0; k8 < 8; ++k8) {
            const int kk = k8 * 8 + lc;
            uint32_t af[2][4], bf[4][2];
#pragma unroll
            for (int mt = 0; mt < 2; ++mt) {
                int r = wm * 32 + mt * 16 + lr;
                af[mt][0] = __float_as_uint(st[r * 68 + kk]);
                af[mt][1] = __float_as_uint(st[(r + 8) * 68 + kk]);
                af[mt][2] = __float_as_uint(st[r * 68 + kk + 4]);
                af[mt][3] = __float_as_uint(st[(r + 8) * 68 + kk + 4]);
            }
#pragma unroll
            for (int nt = 0; nt < 4; ++nt) {
                int n = wn * 32 + nt * 8 + lr;
                bf[nt][0] = __float_as_uint(sa[n * 68 + kk]);
                bf[nt][1] = __float_as_uint(sa[n * 68 + kk + 4]);
            }
#pragma unroll
            for (int mt = 0; mt < 2; ++mt)
#pragma unroll
                for (int nt = 0; nt < 4; ++nt) mma8(acc[mt][nt], af[mt], bf[nt]);
        }

        float2 bv[4];
#pragma unroll
        for (int nt = 0; nt < 4; ++nt)
            bv[nt] = *reinterpret_cast<const float2*>(&bias[out0 + wn * 32 + nt * 8 + 2 * lc]);

#pragma unroll
        for (int mt = 0; mt < 2; ++mt)
#pragma unroll
            for (int h = 0; h < 2; ++h) {
                int r = tok0 + wm * 32 + mt * 16 + lr + 8 * h;
                float* yr = y + (size_t)r * 4096 + out0 + wn * 32;
#pragma unroll
                for (int nt = 0; nt < 4; ++nt) {
                    *reinterpret_cast<float2*>(&yr[nt * 8 + 2 * lc]) =
                        make_float2(acc[mt][nt][2 * h] + bv[nt].x,
                                    acc[mt][nt][2 * h + 1] + bv[nt].y);
                }
            }
        __syncthreads();      // buffer (c&1) free before chunk c+2 is issued
    }
}

// ---------------------------------------------------------------------------
// Launch
// ---------------------------------------------------------------------------
extern "C" void kernel_launch(void* const* d_in, const int* in_sizes, int n_in,
                              void* d_out, int out_size) {
    const float* core[6] = {nullptr, nullptr, nullptr, nullptr, nullptr, nullptr};
    const float* x = nullptr;
    const float* bias = nullptr;
    int c64 = 1;
    for (int i = 0; i < n_in; ++i) {
        int sz = in_sizes[i];
        const float* p = reinterpret_cast<const float*>(d_in[i]);
        if (sz == 8192 * 4096) x = p;
        else if (sz == 4096) bias = p;
        else if (sz == 65536) { if (c64 <= 4) core[c64++] = p; }
        else if (sz == 1024) { if (!core[0]) core[0] = p; else core[5] = p; }
    }
    float* y = reinterpret_cast<float*>(d_out);

    const int g1_smem = 4 * 27648;                       // 110592
    const int g2_smem = 17408 + 2 * 34816;               // 87040 -> 2 CTAs/SM
    cudaFuncSetAttribute(gemm1_kernel, cudaFuncAttributeMaxDynamicSharedMemorySize, g1_smem);
    cudaFuncSetAttribute(gemm2_kernel, cudaFuncAttributeMaxDynamicSharedMemorySize, g2_smem);
    cudaFuncSetAttribute(gemm1_kernel, cudaFuncAttributePreferredSharedMemoryCarveout, 100);
    cudaFuncSetAttribute(gemm2_kernel, cudaFuncAttributePreferredSharedMemoryCarveout, 100);

    foldG45_kernel<<<64, 256>>>(core[4], core[5]);
    foldB_kernel<<<1024, 256>>>(core[3]);
    gemm1_kernel<<<148, 256, g1_smem>>>(x, core[0], core[1], core[2]);
    gemm2_kernel<<<dim3(128, 8), 256, g2_smem>>>(bias, y);
}

// round 17
// speedup vs baseline: 1.9067x; 1.4352x over previous
#include <cuda_runtime.h>
#include <cuda_fp16.h>
#include <cstdint>

// ===========================================================================
// TT-linear via rank-64 bottleneck:  W = A(4096x64) @ B(64x4096)
// fp16 m16n8k16 mma (2048 MAC/instr -> half the instruction count of tf32-k8;
// same 10-bit mantissa as tf32 -> same accuracy).
//   t = x @ B^T      (split-K=2, 4-stage cp.async ring; x fp32->h2 at frag build)
//   y = t @ A^T + b  (64tok x 4x128out chunks, A dbl-buffered)
// ===========================================================================
__device__ __align__(256) __half g_Ah[4096 * 64];   // A (out, r)  fp16
__device__ __align__(256) float  g_G45[64 * 256];   // fold(core4,core5)
__device__ __align__(256) __half g_Bh[64 * 4096];   // B (r, in)   fp16
__device__ __align__(256) float  g_T[2][8192 * 64]; // split-K=2 fp32 partials of t

// ---------------- helpers ---------------------------------------------------
__device__ __forceinline__ uint32_t smem_u32(const void* p) {
    uint32_t a;
    asm("{ .reg .u64 t; cvta.to.shared.u64 t, %1; cvt.u32.u64 %0, t; }" : "=r"(a) : "l"(p));
    return a;
}
__device__ __forceinline__ void cp16(uint32_t dst, const void* src) {
    asm volatile("cp.async.cg.shared.global [%0], [%1], 16;" :: "r"(dst), "l"(src));
}
#define CP_COMMIT() asm volatile("cp.async.commit_group;" ::: "memory")
#define CP_WAIT2()  asm volatile("cp.async.wait_group 2;" ::: "memory")
#define CP_WAIT1()  asm volatile("cp.async.wait_group 1;" ::: "memory")
#define CP_WAIT0()  asm volatile("cp.async.wait_group 0;" ::: "memory")

// D += A * B   (m16n8k16, fp16 inputs, f32 accum)
__device__ __forceinline__ void mma16(float* c, const uint32_t* a, const uint32_t* b) {
    asm volatile(
        "mma.sync.aligned.m16n8k16.row.col.f32.f16.f16.f32 "
        "{%0,%1,%2,%3}, {%4,%5,%6,%7}, {%8,%9}, {%0,%1,%2,%3};"
        : "+f"(c[0]), "+f"(c[1]), "+f"(c[2]), "+f"(c[3])
        : "r"(a[0]), "r"(a[1]), "r"(a[2]), "r"(a[3]), "r"(b[0]), "r"(b[1]));
}

__device__ __forceinline__ uint32_t pack_h2(float lo, float hi) {
    __half2 h = __floats2half2_rn(lo, hi);      // .x = lo, .y = hi
    return *reinterpret_cast<uint32_t*>(&h);
}

// ---------------------------------------------------------------------------
// Folds. Cores: G0(1,16,64) G1..G4(64,16,64) G5(64,16,1).
// ---------------------------------------------------------------------------
__global__ void foldG45_kernel(const float* __restrict__ G4, const float* __restrict__ G5) {
    int i = blockIdx.x * 256 + threadIdx.x;       // 16384: G45[r4][(s4,s5)]
    int r4 = i >> 8, s4 = (i >> 4) & 15, s5 = i & 15;
    float s = 0.f;
#pragma unroll
    for (int r5 = 0; r5 < 64; ++r5) s += G4[r4 * 1024 + s4 * 64 + r5] * G5[r5 * 16 + s5];
    g_G45[i] = s;
}

// blocks [0,1024) = foldB -> g_Bh; blocks [1024,2048) = fold12 (A) -> g_Ah.
__global__ __launch_bounds__(256) void foldB12_kernel(const float* __restrict__ G3,
                                                      const float* __restrict__ G0,
                                                      const float* __restrict__ G1,
                                                      const float* __restrict__ G2) {
    const int tid = threadIdx.x;
    if (blockIdx.x < 1024) {
        // B[(r3,s3)][(s4,s5)]: flat (1024,256) == (64,4096) row-major.
        const int b = blockIdx.x, c = tid;
        float a0 = 0.f, a1 = 0.f, a2 = 0.f, a3 = 0.f;
#pragma unroll
        for (int r4 = 0; r4 < 64; r4 += 4) {
            a0 += G3[b * 64 + r4]     * g_G45[r4 * 256 + c];
            a1 += G3[b * 64 + r4 + 1] * g_G45[(r4 + 1) * 256 + c];
            a2 += G3[b * 64 + r4 + 2] * g_G45[(r4 + 2) * 256 + c];
            a3 += G3[b * 64 + r4 + 3] * g_G45[(r4 + 3) * 256 + c];
        }
        g_Bh[(size_t)b * 256 + c] = __float2half_rn((a0 + a1) + (a2 + a3));
    } else {
        // A[(s0,s1)][(s2,r3)]: flat (256,1024) == (4096,64) row-major.
        __shared__ float w01row[64];
        const int b = blockIdx.x - 1024;
        const int r = b >> 2, s0 = r >> 4, s1 = r & 15;
        if (tid < 64) {
            float s = 0.f;
#pragma unroll
            for (int r1 = 0; r1 < 64; ++r1)
                s += G0[s0 * 64 + r1] * G1[r1 * 1024 + s1 * 64 + tid];
            w01row[tid] = s;
        }
        __syncthreads();
        const int c = (b & 3) * 256 + tid;
        float a0 = 0.f, a1 = 0.f, a2 = 0.f, a3 = 0.f;
#pragma unroll
        for (int r2 = 0; r2 < 64; r2 += 4) {
            a0 += w01row[r2]     * G2[r2 * 1024 + c];
            a1 += w01row[r2 + 1] * G2[(r2 + 1) * 1024 + c];
            a2 += w01row[r2 + 2] * G2[(r2 + 2) * 1024 + c];
            a3 += w01row[r2 + 3] * G2[(r2 + 3) * 1024 + c];
        }
        g_Ah[(size_t)r * 1024 + c] = __float2half_rn((a0 + a1) + (a2 + a3));
    }
}

// ---------------------------------------------------------------------------
// GEMM1: t[n,r] = sum_k x[n,k]*B[r,k].  M=8192 N=64 K=4096, split-K=2.
// grid (64,2), 256 threads, 8 warps 4x2, warp tile 32x32. K chunks of 32
// (two m16n8k16 steps), 4-stage cp.async ring.
// Stage layout: x fp32 128 rows x 144B (18432B) then B fp16 64 rows x 80B
// (5120B); stride 23552B. x packed to half2 at fragment build.
// ---------------------------------------------------------------------------
__global__ __launch_bounds__(256) void gemm1_kernel(const float* __restrict__ x) {
    extern __shared__ char sm[];
    const uint32_t sb = smem_u32(sm);
    const int tid = threadIdx.x;
    const int warp = tid >> 5, lane = tid & 31;
    const int wm = warp >> 1, wn = warp & 1;      // warp origin (wm*32, wn*32)
    const int tok0 = blockIdx.x * 128;
    const int kbase = blockIdx.y * 2048;
    const int qr = (tid & 7) * 4;
    const int row0 = tid >> 3;                    // 0..31

    float acc[2][4][4];
#pragma unroll
    for (int a = 0; a < 2; ++a)
#pragma unroll
        for (int b = 0; b < 4; ++b)
#pragma unroll
            for (int c = 0; c < 4; ++c) acc[a][b][c] = 0.f;

    auto issue = [&](int chunk, int s) {
        int kc = kbase + chunk * 32;
        uint32_t xd = sb + s * 23552;
        uint32_t bd = xd + 18432;
#pragma unroll
        for (int l = 0; l < 4; ++l) {
            int r = row0 + 32 * l;
            cp16(xd + (uint32_t)(r * 144 + qr * 4), &x[(size_t)(tok0 + r) * 4096 + kc + qr]);
        }
        {   // B: 64 rows x 64B (32 halves) = 256 x 16B, one per thread
            int r = tid >> 2, blk = tid & 3;
            cp16(bd + (uint32_t)(r * 80 + blk * 16), &g_Bh[(size_t)r * 4096 + kc + blk * 8]);
        }
    };

    issue(0, 0); CP_COMMIT();
    issue(1, 1); CP_COMMIT();
    issue(2, 2); CP_COMMIT();

    const int lr = lane >> 2, lc = lane & 3;
    for (int i = 0; i < 64; ++i) {
        CP_WAIT2();
        __syncthreads();
        if (i + 3 < 64) issue(i + 3, (i + 3) & 3);
        CP_COMMIT();    // empty group at tail keeps wait_group 2 uniform

        const float* xs = reinterpret_cast<const float*>(sm + (i & 3) * 23552);
        const __half* bs = reinterpret_cast<const __half*>(sm + (i & 3) * 23552 + 18432);
#pragma unroll
        for (int ks = 0; ks < 2; ++ks) {
            const int k0 = ks * 16 + 2 * lc;
            uint32_t af[2][4], bf[4][2];
#pragma unroll
            for (int mt = 0; mt < 2; ++mt) {
                int r = wm * 32 + mt * 16 + lr;
                const float* p0 = &xs[r * 36 + k0];
                const float* p1 = &xs[(r + 8) * 36 + k0];
                af[mt][0] = pack_h2(p0[0], p0[1]);
                af[mt][1] = pack_h2(p1[0], p1[1]);
                af[mt][2] = pack_h2(p0[8], p0[9]);
                af[mt][3] = pack_h2(p1[8], p1[9]);
            }
#pragma unroll
            for (int nt = 0; nt < 4; ++nt) {
                int n = wn * 32 + nt * 8 + lr;
                bf[nt][0] = *reinterpret_cast<const uint32_t*>(&bs[n * 40 + k0]);
                bf[nt][1] = *reinterpret_cast<const uint32_t*>(&bs[n * 40 + k0 + 8]);
            }
#pragma unroll
            for (int mt = 0; mt < 2; ++mt)
#pragma unroll
                for (int nt = 0; nt < 4; ++nt) mma16(acc[mt][nt], af[mt], bf[nt]);
        }
    }

    float* tp = g_T[blockIdx.y];
#pragma unroll
    for (int mt = 0; mt < 2; ++mt)
#pragma unroll
        for (int nt = 0; nt < 4; ++nt)
#pragma unroll
            for (int h = 0; h < 2; ++h) {
                int r = tok0 + wm * 32 + mt * 16 + lr + 8 * h;
                int c = wn * 32 + nt * 8 + 2 * lc;
                *reinterpret_cast<float2*>(&tp[(size_t)r * 64 + c]) =
                    make_float2(acc[mt][nt][2 * h], acc[mt][nt][2 * h + 1]);
            }
}

// ---------------------------------------------------------------------------
// GEMM2: y[n,o] = sum_r t[n,r]*A[o,r] + b[o].  M=8192 N=4096 K=64.
// grid (128,8) = 1024 CTAs, 256 threads, 8 warps 2x4 (warp 32x32 per chunk).
// CTA: 64 tok x 512 outs as 4 chunks of 128; t loaded once (partials summed,
// converted to fp16); A fp16 chunks cp.async double-buffered.
// smem: t fp16 64 rows x 144B @0 (9216B), A bufs @9216/@27648 (128x144B each)
// = 46080B total.
// ---------------------------------------------------------------------------
__global__ __launch_bounds__(256) void gemm2_kernel(const float* __restrict__ bias,
                                                    float* __restrict__ y) {
    extern __shared__ char sm[];
    __half* st = reinterpret_cast<__half*>(sm);   // [64][72 halves]
    const uint32_t sb = smem_u32(sm);
    const int tid = threadIdx.x;
    const int warp = tid >> 5, lane = tid & 31;
    const int wm = warp >> 2, wn = warp & 3;      // warp origin (wm*32, wn*32)
    const int tok0 = blockIdx.x * 64;
    const int outbase = blockIdx.y * 512;
    const int lr = lane >> 2, lc = lane & 3;

    // A chunk (128 outs x 64 halves = 128B/row) into buffer buf: 1024 x 16B
    auto issueA = [&](int chunk, int buf) {
        const __half* src = &g_Ah[(size_t)(outbase + chunk * 128) * 64];
        uint32_t base = sb + 9216 + buf * 18432;
#pragma unroll
        for (int l = 0; l < 4; ++l) {
            int s = tid + 256 * l;        // 0..1023
            int row = s >> 3, blk = s & 7;
            cp16(base + (uint32_t)(row * 144 + blk * 16), src + (size_t)row * 64 + blk * 8);
        }
    };

    issueA(0, 0); CP_COMMIT();

    // t tile: reduce split-K partials, convert to fp16 (overlaps A0 fetch)
#pragma unroll
    for (int l = 0; l < 4; ++l) {
        int s = tid + 256 * l, row = s >> 4, q = (s & 15) * 4;
        size_t off = (size_t)(tok0 + row) * 64 + q;
        float4 v0 = *reinterpret_cast<const float4*>(&g_T[0][off]);
        float4 v1 = *reinterpret_cast<const float4*>(&g_T[1][off]);
        uint2 pk;
        pk.x = pack_h2(v0.x + v1.x, v0.y + v1.y);
        pk.y = pack_h2(v0.z + v1.z, v0.w + v1.w);
        *reinterpret_cast<uint2*>(&st[row * 72 + q]) = pk;
    }

#pragma unroll
    for (int c = 0; c < 4; ++c) {
        if (c < 3) { issueA(c + 1, (c + 1) & 1); CP_COMMIT(); CP_WAIT1(); }
        else       { CP_WAIT0(); }
        __syncthreads();      // chunk c ready for all warps

        const __half* sa = reinterpret_cast<const __half*>(sm + 9216 + (c & 1) * 18432);
        const int out0 = outbase + c * 128;

        float acc[2][4][4];
#pragma unroll
        for (int a = 0; a < 2; ++a)
#pragma unroll
            for (int b = 0; b < 4; ++b)
#pragma unroll
                for (int q = 0; q < 4; ++q) acc[a][b][q] = 0.f;

#pragma unroll
        for (int ks = 0; ks < 4; ++ks) {
            const int k0 = ks * 16 + 2 * lc;
            uint32_t af[2][4], bf[4][2];
#pragma unroll
            for (int mt = 0; mt < 2; ++mt) {
                int r = wm * 32 + mt * 16 + lr;
                af[mt][0] = *reinterpret_cast<const uint32_t*>(&st[r * 72 + k0]);
                af[mt][1] = *reinterpret_cast<const uint32_t*>(&st[(r + 8) * 72 + k0]);
                af[mt][2] = *reinterpret_cast<const uint32_t*>(&st[r * 72 + k0 + 8]);
                af[mt][3] = *reinterpret_cast<const uint32_t*>(&st[(r + 8) * 72 + k0 + 8]);
            }
#pragma unroll
            for (int nt = 0; nt < 4; ++nt) {
                int n = wn * 32 + nt * 8 + lr;
                bf[nt][0] = *reinterpret_cast<const uint32_t*>(&sa[n * 72 + k0]);
                bf[nt][1] = *reinterpret_cast<const uint32_t*>(&sa[n * 72 + k0 + 8]);
            }
#pragma unroll
            for (int mt = 0; mt < 2; ++mt)
#pragma unroll
                for (int nt = 0; nt < 4; ++nt) mma16(acc[mt][nt], af[mt], bf[nt]);
        }

        float2 bv[4];
#pragma unroll
        for (int nt = 0; nt < 4; ++nt)
            bv[nt] = *reinterpret_cast<const float2*>(&bias[out0 + wn * 32 + nt * 8 + 2 * lc]);

#pragma unroll
        for (int mt = 0; mt < 2; ++mt)
#pragma unroll
            for (int h = 0; h < 2; ++h) {
                int r = tok0 + wm * 32 + mt * 16 + lr + 8 * h;
                float* yr = y + (size_t)r * 4096 + out0 + wn * 32;
#pragma unroll
                for (int nt = 0; nt < 4; ++nt) {
                    *reinterpret_cast<float2*>(&yr[nt * 8 + 2 * lc]) =
                        make_float2(acc[mt][nt][2 * h] + bv[nt].x,
                                    acc[mt][nt][2 * h + 1] + bv[nt].y);
                }
            }
        __syncthreads();      // buffer (c&1) free before chunk c+2 is issued
    }
}

// ---------------------------------------------------------------------------
// Launch
// ---------------------------------------------------------------------------
extern "C" void kernel_launch(void* const* d_in, const int* in_sizes, int n_in,
                              void* d_out, int out_size) {
    const float* core[6] = {nullptr, nullptr, nullptr, nullptr, nullptr, nullptr};
    const float* x = nullptr;
    const float* bias = nullptr;
    int c64 = 1;
    for (int i = 0; i < n_in; ++i) {
        int sz = in_sizes[i];
        const float* p = reinterpret_cast<const float*>(d_in[i]);
        if (sz == 8192 * 4096) x = p;
        else if (sz == 4096) bias = p;
        else if (sz == 65536) { if (c64 <= 4) core[c64++] = p; }
        else if (sz == 1024) { if (!core[0]) core[0] = p; else core[5] = p; }
    }
    float* y = reinterpret_cast<float*>(d_out);

    const int g1_smem = 4 * 23552;                // 94208
    const int g2_smem = 9216 + 2 * 18432;         // 46080
    cudaFuncSetAttribute(gemm1_kernel, cudaFuncAttributeMaxDynamicSharedMemorySize, g1_smem);
    cudaFuncSetAttribute(gemm2_kernel, cudaFuncAttributeMaxDynamicSharedMemorySize, g2_smem);
    cudaFuncSetAttribute(gemm1_kernel, cudaFuncAttributePreferredSharedMemoryCarveout, 100);
    cudaFuncSetAttribute(gemm2_kernel, cudaFuncAttributePreferredSharedMemoryCarveout, 100);

    foldG45_kernel<<<64, 256>>>(core[4], core[5]);
    foldB12_kernel<<<2048, 256>>>(core[3], core[0], core[1], core[2]);
    gemm1_kernel<<<dim3(64, 2), 256, g1_smem>>>(x);
    gemm2_kernel<<<dim3(128, 8), 256, g2_smem>>>(bias, y);
}